// round 4
// baseline (speedup 1.0000x reference)
#include <cuda_runtime.h>
#include <math.h>

#define NN 50000
#define EE 800000
#define GG 1024
#define DD 64
#define DIN 9
#define NBLK ((NN + 255) / 256)   // 196

// ---------------- scratch (static device globals; no allocation) ------------
__device__ int      g_deg[NN];        // degree incl. self-loop
__device__ float    g_dinv[NN];
__device__ int      g_ptr[NN];        // CSR row (by destination) start
__device__ int      g_pos[NN];        // fill counters
__device__ int      g_srcs[EE];       // CSR column: source node per in-edge
__device__ int      g_bsum[NBLK];     // scan block sums
__device__ float    g_feat[NN * DD];  // current node features
__device__ float    g_agg[NN * DD];   // aggregation buffer (also used K=9)
__device__ unsigned g_gmax[GG * DD];
__device__ float    g_gsum[GG * DD];
__device__ int      g_gcnt[GG];

// ---------------- setup kernels --------------------------------------------
__global__ void k_init() {
    int i = blockIdx.x * blockDim.x + threadIdx.x;   // grid covers 65536
    if (i < NN) { g_deg[i] = 1; g_pos[i] = 0; }
    if (i < GG * DD) { g_gmax[i] = 0u; g_gsum[i] = 0.f; }
    if (i < GG) g_gcnt[i] = 0;
}

__global__ void k_degcount(const int* __restrict__ ei) {
    int e = blockIdx.x * blockDim.x + threadIdx.x;
    if (e < EE) atomicAdd(&g_deg[ei[EE + e]], 1);    // destination
}

__global__ void k_scan1() {
    __shared__ int sh[256];
    int i = blockIdx.x * 256 + threadIdx.x;
    int v = (i < NN) ? (g_deg[i] - 1) : 0;           // in-edge count (no self)
    sh[threadIdx.x] = v;
    __syncthreads();
    for (int o = 1; o < 256; o <<= 1) {
        int t = (threadIdx.x >= o) ? sh[threadIdx.x - o] : 0;
        __syncthreads();
        sh[threadIdx.x] += t;
        __syncthreads();
    }
    if (i < NN) g_ptr[i] = sh[threadIdx.x] - v;      // exclusive within block
    if (threadIdx.x == 255) g_bsum[blockIdx.x] = sh[255];
}

__global__ void k_scan2() {
    __shared__ int sh[256];
    int t = threadIdx.x;
    int v = (t < NBLK) ? g_bsum[t] : 0;
    sh[t] = v;
    __syncthreads();
    for (int o = 1; o < 256; o <<= 1) {
        int x = (t >= o) ? sh[t - o] : 0;
        __syncthreads();
        sh[t] += x;
        __syncthreads();
    }
    if (t < NBLK) g_bsum[t] = sh[t] - v;             // exclusive block offsets
}

__global__ void k_scan3() {
    int i = blockIdx.x * 256 + threadIdx.x;
    if (i < NN) {
        g_ptr[i] += g_bsum[blockIdx.x];
        g_dinv[i] = rsqrtf((float)g_deg[i]);
    }
}

__global__ void k_fill(const int* __restrict__ ei) {
    int e = blockIdx.x * blockDim.x + threadIdx.x;
    if (e < EE) {
        int d = ei[EE + e];
        int p = g_ptr[d] + atomicAdd(&g_pos[d], 1);
        g_srcs[p] = ei[e];                           // source
    }
}

// ---------------- aggregation: out[v] = dinv[v]*(sum dinv[s]*feat[s] + dinv[v]*feat[v])
__global__ void k_agg9(const float* __restrict__ feat, float* __restrict__ out) {
    int w = (blockIdx.x * blockDim.x + threadIdx.x) >> 5;
    int lane = threadIdx.x & 31;
    if (w >= NN) return;
    int start = g_ptr[w];
    int cnt = g_deg[w] - 1;
    float di = g_dinv[w];
    float a = 0.f;
    for (int i = 0; i < cnt; i++) {
        int s = g_srcs[start + i];
        float ws = g_dinv[s];
        if (lane < DIN) a += ws * feat[s * DIN + lane];
    }
    if (lane < DIN) {
        a += di * feat[w * DIN + lane];
        out[w * DIN + lane] = di * a;
    }
}

__global__ void k_agg64(const float* __restrict__ feat, float* __restrict__ out) {
    int w = (blockIdx.x * blockDim.x + threadIdx.x) >> 5;
    int lane = threadIdx.x & 31;
    if (w >= NN) return;
    int start = g_ptr[w];
    int cnt = g_deg[w] - 1;
    float di = g_dinv[w];
    float ax = 0.f, ay = 0.f;
    int i = 0;
    // 4-wide software pipeline for MLP
    for (; i + 4 <= cnt; i += 4) {
        int s0 = g_srcs[start + i];
        int s1 = g_srcs[start + i + 1];
        int s2 = g_srcs[start + i + 2];
        int s3 = g_srcs[start + i + 3];
        float w0 = g_dinv[s0], w1 = g_dinv[s1], w2 = g_dinv[s2], w3 = g_dinv[s3];
        float2 v0 = ((const float2*)(feat + s0 * DD))[lane];
        float2 v1 = ((const float2*)(feat + s1 * DD))[lane];
        float2 v2 = ((const float2*)(feat + s2 * DD))[lane];
        float2 v3 = ((const float2*)(feat + s3 * DD))[lane];
        ax += w0 * v0.x + w1 * v1.x + w2 * v2.x + w3 * v3.x;
        ay += w0 * v0.y + w1 * v1.y + w2 * v2.y + w3 * v3.y;
    }
    for (; i < cnt; i++) {
        int s = g_srcs[start + i];
        float ws = g_dinv[s];
        float2 v = ((const float2*)(feat + s * DD))[lane];
        ax += ws * v.x;
        ay += ws * v.y;
    }
    float2 vs = ((const float2*)(feat + w * DD))[lane];
    ax += di * vs.x;
    ay += di * vs.y;
    float2 o;
    o.x = di * ax;
    o.y = di * ay;
    ((float2*)(out + w * DD))[lane] = o;
}

// ---------------- dense: out[n,c] = tanh(sum_k A[n,k]*W[k,c] + b[c]) --------
template <int K>
__global__ void k_gemm(const float* __restrict__ A, const float* __restrict__ W,
                       const float* __restrict__ b, float* __restrict__ out) {
    __shared__ float Ws[K * DD];
    __shared__ float As[4 * K];
    int tid = threadIdx.x;                       // 256
    for (int i = tid; i < K * DD; i += 256) Ws[i] = W[i];
    int node0 = blockIdx.x * 4;
    for (int i = tid; i < 4 * K; i += 256) {
        int n = node0 + i / K;
        As[i] = (n < NN) ? A[n * K + i % K] : 0.f;
    }
    __syncthreads();
    int local = tid >> 6, col = tid & 63;
    int node = node0 + local;
    if (node < NN) {
        float acc = b[col];
#pragma unroll
        for (int k = 0; k < K; k++) acc = fmaf(As[local * K + k], Ws[k * DD + col], acc);
        out[node * DD + col] = tanhf(acc);
    }
}

// ---------------- pooling ---------------------------------------------------
__global__ void k_cnt(const int* __restrict__ batch) {
    int n = blockIdx.x * blockDim.x + threadIdx.x;
    if (n < NN) atomicAdd(&g_gcnt[batch[n]], 1);
}

__global__ void k_pool(const int* __restrict__ batch) {
    int idx = blockIdx.x * blockDim.x + threadIdx.x;   // N*64
    if (idx >= NN * DD) return;
    int n = idx >> 6, f = idx & 63;
    int g = batch[n];
    float v = g_feat[idx];
    unsigned enc = (v >= 0.f) ? (__float_as_uint(v) | 0x80000000u)
                              : ~__float_as_uint(v);
    atomicMax(&g_gmax[g * DD + f], enc);
    atomicAdd(&g_gsum[g * DD + f], v);
}

__global__ void k_out(const float* __restrict__ Wout, const float* __restrict__ bout,
                      float* __restrict__ out) {
    int g = blockIdx.x;                          // GG blocks x 32 threads
    int lane = threadIdx.x;
    float cnt = fmaxf((float)g_gcnt[g], 1.f);
    float s = 0.f;
    for (int f = lane; f < DD; f += 32) {
        unsigned e = g_gmax[g * DD + f];
        float mx = (e & 0x80000000u) ? __uint_as_float(e & 0x7FFFFFFFu)
                                     : __uint_as_float(~e);
        float mn = g_gsum[g * DD + f] / cnt;
        s += mx * Wout[f] + mn * Wout[DD + f];
    }
#pragma unroll
    for (int o = 16; o > 0; o >>= 1) s += __shfl_down_sync(0xFFFFFFFFu, s, o);
    if (lane == 0) out[g] = s + bout[0];
}

// ---------------- launch ----------------------------------------------------
extern "C" void kernel_launch(void* const* d_in, const int* in_sizes, int n_in,
                              void* d_out, int out_size) {
    const float* x     = (const float*)d_in[0];
    const int*   ei    = (const int*)d_in[1];
    const int*   batch = (const int*)d_in[2];
    const float* W0    = (const float*)d_in[3];
    const float* b0    = (const float*)d_in[4];
    const float* W1    = (const float*)d_in[5];
    const float* b1    = (const float*)d_in[6];
    const float* W2    = (const float*)d_in[7];
    const float* b2    = (const float*)d_in[8];
    const float* W3    = (const float*)d_in[9];
    const float* b3    = (const float*)d_in[10];
    const float* Wout  = (const float*)d_in[11];
    const float* bout  = (const float*)d_in[12];
    float* out = (float*)d_out;

    // device-global pointers for feat/agg
    float *featp, *aggp;
    cudaGetSymbolAddress((void**)&featp, g_feat);
    cudaGetSymbolAddress((void**)&aggp, g_agg);

    const int EB = (EE + 255) / 256;              // 3125

    k_init<<<256, 256>>>();
    k_degcount<<<EB, 256>>>(ei);
    k_scan1<<<NBLK, 256>>>();
    k_scan2<<<1, 256>>>();
    k_scan3<<<NBLK, 256>>>();
    k_fill<<<EB, 256>>>(ei);

    const int AGGB = (NN * 32 + 255) / 256;       // 6250 (warp per node)
    const int GEMB = (NN + 3) / 4;                // 12500

    // layer 0: aggregate raw 9-dim features, then GEMM K=9
    k_agg9<<<AGGB, 256>>>(x, aggp);
    k_gemm<DIN><<<GEMB, 256>>>(aggp, W0, b0, featp);
    // layers 1..3
    k_agg64<<<AGGB, 256>>>(featp, aggp);
    k_gemm<DD><<<GEMB, 256>>>(aggp, W1, b1, featp);
    k_agg64<<<AGGB, 256>>>(featp, aggp);
    k_gemm<DD><<<GEMB, 256>>>(aggp, W2, b2, featp);
    k_agg64<<<AGGB, 256>>>(featp, aggp);
    k_gemm<DD><<<GEMB, 256>>>(aggp, W3, b3, featp);

    // pooling + readout
    k_cnt<<<NBLK, 256>>>(batch);
    k_pool<<<(NN * DD + 255) / 256, 256>>>(batch);
    k_out<<<GG, 32>>>(Wout, bout, out);
}

// round 6
// speedup vs baseline: 1.0636x; 1.0636x over previous
#include <cuda_runtime.h>
#include <cuda_fp16.h>
#include <math.h>

#define NN 50000
#define EE 800000
#define GG 1024
#define DD 64
#define DIN 9
#define NBLK ((NN + 255) / 256)   // 196

// ---------------- scratch (static device globals; no allocation) ------------
__device__ int      g_deg[NN];        // degree incl. self-loop
__device__ float    g_dinv[NN];
__device__ int      g_ptr[NN];        // CSR (by destination) segment start
__device__ int      g_pos[NN];        // fill counters
__device__ int      g_srcs[EE];       // CSR column: source node per in-edge
__device__ int      g_total;          // bump allocator
__device__ __align__(16) __half g_feat[NN * DD];  // features, pre-scaled by dinv
__device__ float    g_agg[NN * DD];   // aggregation output (fp32)
__device__ unsigned g_gmax[GG * DD];
__device__ float    g_gsum[GG * DD];
__device__ int      g_gcnt[GG];

// ---------------- setup -----------------------------------------------------
__global__ void k_init() {
    int i = blockIdx.x * blockDim.x + threadIdx.x;   // grid covers 65536
    if (i < NN) { g_deg[i] = 1; g_pos[i] = 0; }
    if (i < GG * DD) { g_gmax[i] = 0u; g_gsum[i] = 0.f; }
    if (i < GG) g_gcnt[i] = 0;
    if (i == 0) g_total = 0;
}

__global__ void k_count(const int* __restrict__ ei, const int* __restrict__ batch) {
    int e = blockIdx.x * blockDim.x + threadIdx.x;
    if (e < EE) atomicAdd(&g_deg[ei[EE + e]], 1);    // destination in-degree
    if (e < NN) atomicAdd(&g_gcnt[batch[e]], 1);     // nodes-per-graph
}

__global__ void k_alloc() {
    int i = blockIdx.x * blockDim.x + threadIdx.x;
    if (i < NN) {
        int c = g_deg[i] - 1;                        // in-edges (no self)
        g_ptr[i] = atomicAdd(&g_total, c);           // contiguous segment
        g_dinv[i] = rsqrtf((float)g_deg[i]);
    }
}

__global__ void k_fill(const int* __restrict__ ei) {
    int e = blockIdx.x * blockDim.x + threadIdx.x;
    if (e < EE) {
        int d = ei[EE + e];
        int p = g_ptr[d] + atomicAdd(&g_pos[d], 1);
        g_srcs[p] = ei[e];                           // source
    }
}

// ---------------- layer-0 aggregation over raw 9-dim x ----------------------
// out[v] = dinv[v] * ( sum_s dinv[s]*x[s] + dinv[v]*x[v] )
__global__ void k_agg9(const float* __restrict__ x, float* __restrict__ out) {
    int w = (blockIdx.x * blockDim.x + threadIdx.x) >> 5;
    int lane = threadIdx.x & 31;
    if (w >= NN) return;
    int start = g_ptr[w], cnt = g_deg[w] - 1;
    float a = 0.f;
    for (int base = 0; base < cnt; base += 32) {
        int m = min(32, cnt - base);
        int sl = 0; float dl = 0.f;
        if (lane < m) { sl = g_srcs[start + base + lane]; dl = g_dinv[sl]; }
        for (int i = 0; i < m; i++) {
            int s   = __shfl_sync(0xffffffffu, sl, i);
            float ws = __shfl_sync(0xffffffffu, dl, i);
            if (lane < DIN) a += ws * x[s * DIN + lane];
        }
    }
    float di = g_dinv[w];
    if (lane < DIN) {
        a += di * x[w * DIN + lane];
        out[w * DIN + lane] = di * a;
    }
}

// ---------------- aggregation on pre-scaled fp16 features --------------------
// g_feat holds fs[v] = dinv[v]*h[v]
// out[v] = dinv[v] * ( sum_s fs[s] + fs[v] )      <-- self term is fs[v], NOT di*fs[v]
__global__ void k_agg64h(float* __restrict__ out) {
    int w = (blockIdx.x * blockDim.x + threadIdx.x) >> 5;
    int lane = threadIdx.x & 31;
    if (w >= NN) return;
    int start = g_ptr[w], cnt = g_deg[w] - 1;
    float ax = 0.f, ay = 0.f;
    const __half2* __restrict__ F = (const __half2*)g_feat;
    for (int base = 0; base < cnt; base += 32) {
        int m = min(32, cnt - base);
        int sl = (lane < m) ? g_srcs[start + base + lane] : 0;
        int i = 0;
        for (; i + 4 <= m; i += 4) {
            int s0 = __shfl_sync(0xffffffffu, sl, i);
            int s1 = __shfl_sync(0xffffffffu, sl, i + 1);
            int s2 = __shfl_sync(0xffffffffu, sl, i + 2);
            int s3 = __shfl_sync(0xffffffffu, sl, i + 3);
            __half2 v0 = F[s0 * 32 + lane];
            __half2 v1 = F[s1 * 32 + lane];
            __half2 v2 = F[s2 * 32 + lane];
            __half2 v3 = F[s3 * 32 + lane];
            float2 f0 = __half22float2(v0), f1 = __half22float2(v1);
            float2 f2 = __half22float2(v2), f3 = __half22float2(v3);
            ax += (f0.x + f1.x) + (f2.x + f3.x);
            ay += (f0.y + f1.y) + (f2.y + f3.y);
        }
        for (; i < m; i++) {
            int s = __shfl_sync(0xffffffffu, sl, i);
            float2 f = __half22float2(F[s * 32 + lane]);
            ax += f.x; ay += f.y;
        }
    }
    float di = g_dinv[w];
    float2 fs = __half22float2(F[w * 32 + lane]);
    ax += fs.x;                    // self-loop contribution = fs[v] (already dinv-scaled)
    ay += fs.y;
    float2 o; o.x = di * ax; o.y = di * ay;
    ((float2*)(out + w * DD))[lane] = o;
}

// ---------------- layer-0 GEMM (K=9): thread-per-node ------------------------
__global__ __launch_bounds__(256) void k_gemm9(const float* __restrict__ A,
        const float* __restrict__ W, const float* __restrict__ b) {
    __shared__ float Ws[DIN * DD];
    __shared__ float bs[DD];
    int tid = threadIdx.x;
    for (int i = tid; i < DIN * DD; i += 256) Ws[i] = W[i];
    if (tid < DD) bs[tid] = b[tid];
    __syncthreads();
    int node = blockIdx.x * 256 + tid;
    if (node >= NN) return;
    float a[DIN];
#pragma unroll
    for (int k = 0; k < DIN; k++) a[k] = A[node * DIN + k];
    float di = g_dinv[node];
    __half2* o = (__half2*)(g_feat + node * DD);
#pragma unroll
    for (int c = 0; c < DD; c += 2) {
        float a0 = bs[c], a1 = bs[c + 1];
#pragma unroll
        for (int k = 0; k < DIN; k++) {
            a0 = fmaf(a[k], Ws[k * DD + c],     a0);
            a1 = fmaf(a[k], Ws[k * DD + c + 1], a1);
        }
        o[c >> 1] = __floats2half2_rn(di * tanhf(a0), di * tanhf(a1));
    }
}

// ---------------- K=64 GEMM: 64-node tile, 4x4 register blocking -------------
// POOL=0: write tanh(.)*dinv as fp16 features. POOL=1: fused graph pooling.
template <int POOL>
__global__ __launch_bounds__(256) void k_gemm64(const float* __restrict__ A,
        const float* __restrict__ W, const float* __restrict__ b,
        const int* __restrict__ batch) {
    __shared__ float As[DD][DD + 4];   // transposed A tile, padded
    __shared__ float Ws[DD * DD];
    int tid = threadIdx.x;
    int node0 = blockIdx.x * DD;
    for (int i = tid; i < DD * DD; i += 256) {
        int n = i >> 6, k = i & 63;
        int node = node0 + n;
        As[k][n] = (node < NN) ? A[node * DD + k] : 0.f;
        Ws[i] = W[i];
    }
    __syncthreads();
    int n0 = (tid >> 4) << 2;
    int c0 = (tid & 15) << 2;
    float4 bv = *(const float4*)(b + c0);
    float acc[4][4];
#pragma unroll
    for (int i = 0; i < 4; i++) {
        acc[i][0] = bv.x; acc[i][1] = bv.y; acc[i][2] = bv.z; acc[i][3] = bv.w;
    }
#pragma unroll
    for (int k = 0; k < DD; k++) {
        float4 av = *(const float4*)&As[k][n0];
        float4 wv = *(const float4*)&Ws[k * DD + c0];
        float aa[4] = {av.x, av.y, av.z, av.w};
        float ww[4] = {wv.x, wv.y, wv.z, wv.w};
#pragma unroll
        for (int i = 0; i < 4; i++)
#pragma unroll
            for (int j = 0; j < 4; j++)
                acc[i][j] = fmaf(aa[i], ww[j], acc[i][j]);
    }
#pragma unroll
    for (int i = 0; i < 4; i++) {
        int node = node0 + n0 + i;
        if (node >= NN) continue;
        float v[4];
#pragma unroll
        for (int j = 0; j < 4; j++) v[j] = tanhf(acc[i][j]);
        if (POOL) {
            int g = batch[node] * DD + c0;
#pragma unroll
            for (int j = 0; j < 4; j++) {
                float x = v[j];
                unsigned enc = (x >= 0.f) ? (__float_as_uint(x) | 0x80000000u)
                                          : ~__float_as_uint(x);
                atomicMax(&g_gmax[g + j], enc);
                atomicAdd(&g_gsum[g + j], x);
            }
        } else {
            float di = g_dinv[node];
            __half2* o = (__half2*)(g_feat + node * DD + c0);
            o[0] = __floats2half2_rn(di * v[0], di * v[1]);
            o[1] = __floats2half2_rn(di * v[2], di * v[3]);
        }
    }
}

// ---------------- readout ----------------------------------------------------
__global__ void k_out(const float* __restrict__ Wout, const float* __restrict__ bout,
                      float* __restrict__ out) {
    int g = blockIdx.x;
    int lane = threadIdx.x;
    float cnt = fmaxf((float)g_gcnt[g], 1.f);
    float s = 0.f;
    for (int f = lane; f < DD; f += 32) {
        unsigned e = g_gmax[g * DD + f];
        float mx = (e & 0x80000000u) ? __uint_as_float(e & 0x7FFFFFFFu)
                                     : __uint_as_float(~e);
        float mn = g_gsum[g * DD + f] / cnt;
        s += mx * Wout[f] + mn * Wout[DD + f];
    }
#pragma unroll
    for (int o = 16; o > 0; o >>= 1) s += __shfl_down_sync(0xFFFFFFFFu, s, o);
    if (lane == 0) out[g] = s + bout[0];
}

// ---------------- launch ----------------------------------------------------
extern "C" void kernel_launch(void* const* d_in, const int* in_sizes, int n_in,
                              void* d_out, int out_size) {
    const float* x     = (const float*)d_in[0];
    const int*   ei    = (const int*)d_in[1];
    const int*   batch = (const int*)d_in[2];
    const float* W0    = (const float*)d_in[3];
    const float* b0    = (const float*)d_in[4];
    const float* W1    = (const float*)d_in[5];
    const float* b1    = (const float*)d_in[6];
    const float* W2    = (const float*)d_in[7];
    const float* b2    = (const float*)d_in[8];
    const float* W3    = (const float*)d_in[9];
    const float* b3    = (const float*)d_in[10];
    const float* Wout  = (const float*)d_in[11];
    const float* bout  = (const float*)d_in[12];
    float* out = (float*)d_out;

    float* aggp;
    cudaGetSymbolAddress((void**)&aggp, g_agg);

    const int EB   = (EE + 255) / 256;        // 3125
    const int AGGB = (NN * 32 + 255) / 256;   // 6250 (warp per node)
    const int GB   = (NN + DD - 1) / DD;      // 782  (64-node GEMM tiles)

    k_init<<<256, 256>>>();
    k_count<<<EB, 256>>>(ei, batch);
    k_alloc<<<NBLK, 256>>>();
    k_fill<<<EB, 256>>>(ei);

    // layer 0: aggregate raw 9-dim features, GEMM K=9, store dinv-scaled fp16
    k_agg9<<<AGGB, 256>>>(x, aggp);
    k_gemm9<<<NBLK, 256>>>(aggp, W0, b0);
    // layers 1..2
    k_agg64h<<<AGGB, 256>>>(aggp);
    k_gemm64<0><<<GB, 256>>>(aggp, W1, b1, nullptr);
    k_agg64h<<<AGGB, 256>>>(aggp);
    k_gemm64<0><<<GB, 256>>>(aggp, W2, b2, nullptr);
    // layer 3 with fused pooling
    k_agg64h<<<AGGB, 256>>>(aggp);
    k_gemm64<1><<<GB, 256>>>(aggp, W3, b3, batch);

    k_out<<<GG, 32>>>(Wout, bout, out);
}

// round 8
// speedup vs baseline: 1.5410x; 1.4489x over previous
#include <cuda_runtime.h>
#include <cuda_fp16.h>
#include <math.h>

#define NN 50000
#define EE 800000
#define GG 1024
#define DD 64
#define DIN 9
#define NBLK ((NN + 255) / 256)   // 196

// ---------------- scratch (static device globals; no allocation) ------------
__device__ int      g_deg[NN];        // in-edge count (no self-loop)
__device__ float    g_dinv[NN];       // rsqrt(in+1)
__device__ int      g_ptr[NN];        // CSR (by destination) segment start
__device__ int      g_pos[NN];        // fill cursor (seeded with start)
__device__ int      g_srcs[EE];       // CSR column: source node per in-edge
__device__ int      g_total;          // bump allocator
__device__ __align__(16) __half g_feat[NN * DD];  // features, pre-scaled by dinv
__device__ float    g_agg[NN * DD];   // aggregation output (fp32)
__device__ unsigned g_gmax[GG * DD];
__device__ float    g_gsum[GG * DD];
__device__ int      g_gcnt[GG];

// ---------------- setup -----------------------------------------------------
__global__ void k_init() {
    int i = blockIdx.x * blockDim.x + threadIdx.x;   // grid covers 65536
    if (i < NN) g_deg[i] = 0;
    if (i < GG * DD) { g_gmax[i] = 0u; g_gsum[i] = 0.f; }
    if (i < GG) g_gcnt[i] = 0;
    if (i == 0) g_total = 0;
}

__global__ void k_count(const int* __restrict__ ei, const int* __restrict__ batch) {
    int e = blockIdx.x * blockDim.x + threadIdx.x;
    if (e < EE) atomicAdd(&g_deg[ei[EE + e]], 1);    // destination in-degree
    if (e < NN) atomicAdd(&g_gcnt[batch[e]], 1);     // nodes-per-graph
}

__global__ void k_alloc() {
    int i = blockIdx.x * blockDim.x + threadIdx.x;
    if (i < NN) {
        int c = g_deg[i];                            // in-edges (no self)
        int s = atomicAdd(&g_total, c);              // contiguous segment
        g_ptr[i] = s;
        g_pos[i] = s;                                // fill cursor
        g_dinv[i] = rsqrtf((float)(c + 1));
    }
}

__global__ void k_fill(const int* __restrict__ ei) {
    int e = blockIdx.x * blockDim.x + threadIdx.x;
    if (e < EE) {
        int d = ei[EE + e];
        int p = atomicAdd(&g_pos[d], 1);
        g_srcs[p] = ei[e];                           // source
    }
}

// ---------------- layer-0 aggregation over raw 9-dim x ----------------------
// out[v] = dinv[v] * ( sum_s dinv[s]*x[s] + dinv[v]*x[v] )
__global__ void k_agg9(const float* __restrict__ x, float* __restrict__ out) {
    int w = (blockIdx.x * blockDim.x + threadIdx.x) >> 5;
    int lane = threadIdx.x & 31;
    if (w >= NN) return;
    int start = g_ptr[w], cnt = g_deg[w];
    float a = 0.f;
    for (int base = 0; base < cnt; base += 32) {
        int m = min(32, cnt - base);
        int sl = 0; float dl = 0.f;
        if (lane < m) { sl = g_srcs[start + base + lane]; dl = g_dinv[sl]; }
        for (int i = 0; i < m; i++) {
            int s   = __shfl_sync(0xffffffffu, sl, i);
            float ws = __shfl_sync(0xffffffffu, dl, i);
            if (lane < DIN) a += ws * x[s * DIN + lane];
        }
    }
    float di = g_dinv[w];
    if (lane < DIN) {
        a += di * x[w * DIN + lane];
        out[w * DIN + lane] = di * a;
    }
}

// ---------------- aggregation on pre-scaled fp16 features --------------------
// g_feat holds fs[v] = dinv[v]*h[v];  out[v] = dinv[v]*( sum_s fs[s] + fs[v] )
// Quad-edge layout: 8 lanes per edge, one uint4 (8 halves) per lane per edge.
__global__ void k_agg64h(float* __restrict__ out) {
    int w = (blockIdx.x * blockDim.x + threadIdx.x) >> 5;
    int lane = threadIdx.x & 31;
    if (w >= NN) return;
    int grp = lane >> 3;          // which edge within quad (0..3)
    int sub = lane & 7;           // dim-chunk (8 halves each)
    int start = g_ptr[w], cnt = g_deg[w];
    const uint4* __restrict__ F = (const uint4*)g_feat;   // node row = 8 uint4
    float acc[8];
#pragma unroll
    for (int j = 0; j < 8; j++) acc[j] = 0.f;

    for (int base = 0; base < cnt; base += 32) {
        int m = min(32, cnt - base);
        int sl = (lane < m) ? g_srcs[start + base + lane] : 0;
        for (int i = 0; i < m; i += 4) {
            int e = i + grp;                              // e <= 34 < 32+3, lane id valid
            int s = __shfl_sync(0xffffffffu, sl, e & 31);
            if (e < m) {
                uint4 v = F[s * 8 + sub];
                float2 f0 = __half22float2(*(const __half2*)&v.x);
                float2 f1 = __half22float2(*(const __half2*)&v.y);
                float2 f2 = __half22float2(*(const __half2*)&v.z);
                float2 f3 = __half22float2(*(const __half2*)&v.w);
                acc[0] += f0.x; acc[1] += f0.y;
                acc[2] += f1.x; acc[3] += f1.y;
                acc[4] += f2.x; acc[5] += f2.y;
                acc[6] += f3.x; acc[7] += f3.y;
            }
        }
    }
    // reduce across the 4 edge-groups (lanes sub, sub+8, sub+16, sub+24)
#pragma unroll
    for (int j = 0; j < 8; j++) {
        acc[j] += __shfl_xor_sync(0xffffffffu, acc[j], 8);
        acc[j] += __shfl_xor_sync(0xffffffffu, acc[j], 16);
    }
    if (grp == 0) {                                       // lanes 0..7 write
        uint4 v = F[w * 8 + sub];                         // self term fs[v]
        float2 f0 = __half22float2(*(const __half2*)&v.x);
        float2 f1 = __half22float2(*(const __half2*)&v.y);
        float2 f2 = __half22float2(*(const __half2*)&v.z);
        float2 f3 = __half22float2(*(const __half2*)&v.w);
        acc[0] += f0.x; acc[1] += f0.y;
        acc[2] += f1.x; acc[3] += f1.y;
        acc[4] += f2.x; acc[5] += f2.y;
        acc[6] += f3.x; acc[7] += f3.y;
        float di = g_dinv[w];
        float4 o0 = {di * acc[0], di * acc[1], di * acc[2], di * acc[3]};
        float4 o1 = {di * acc[4], di * acc[5], di * acc[6], di * acc[7]};
        float4* op = (float4*)(out + w * DD + sub * 8);
        op[0] = o0;
        op[1] = o1;
    }
}

// ---------------- layer-0 GEMM (K=9): thread-per-node ------------------------
__global__ __launch_bounds__(256) void k_gemm9(const float* __restrict__ A,
        const float* __restrict__ W, const float* __restrict__ b) {
    __shared__ float Ws[DIN * DD];
    __shared__ float bs[DD];
    int tid = threadIdx.x;
    for (int i = tid; i < DIN * DD; i += 256) Ws[i] = W[i];
    if (tid < DD) bs[tid] = b[tid];
    __syncthreads();
    int node = blockIdx.x * 256 + tid;
    if (node >= NN) return;
    float a[DIN];
#pragma unroll
    for (int k = 0; k < DIN; k++) a[k] = A[node * DIN + k];
    float di = g_dinv[node];
    __half2* o = (__half2*)(g_feat + node * DD);
#pragma unroll
    for (int c = 0; c < DD; c += 2) {
        float a0 = bs[c], a1 = bs[c + 1];
#pragma unroll
        for (int k = 0; k < DIN; k++) {
            a0 = fmaf(a[k], Ws[k * DD + c],     a0);
            a1 = fmaf(a[k], Ws[k * DD + c + 1], a1);
        }
        o[c >> 1] = __floats2half2_rn(di * tanhf(a0), di * tanhf(a1));
    }
}

// ---------------- K=64 GEMM: 64-node tile, 4x4 register blocking -------------
// POOL=0: write tanh(.)*dinv as fp16 features. POOL=1: fused graph pooling.
template <int POOL>
__global__ __launch_bounds__(256) void k_gemm64(const float* __restrict__ A,
        const float* __restrict__ W, const float* __restrict__ b,
        const int* __restrict__ batch) {
    __shared__ float As[DD][DD + 4];   // transposed A tile, padded
    __shared__ float Ws[DD * DD];
    int tid = threadIdx.x;
    int node0 = blockIdx.x * DD;
    for (int i = tid; i < DD * DD; i += 256) {
        int n = i >> 6, k = i & 63;
        int node = node0 + n;
        As[k][n] = (node < NN) ? A[node * DD + k] : 0.f;
        Ws[i] = W[i];
    }
    __syncthreads();
    int n0 = (tid >> 4) << 2;
    int c0 = (tid & 15) << 2;
    float4 bv = *(const float4*)(b + c0);
    float acc[4][4];
#pragma unroll
    for (int i = 0; i < 4; i++) {
        acc[i][0] = bv.x; acc[i][1] = bv.y; acc[i][2] = bv.z; acc[i][3] = bv.w;
    }
#pragma unroll
    for (int k = 0; k < DD; k++) {
        float4 av = *(const float4*)&As[k][n0];
        float4 wv = *(const float4*)&Ws[k * DD + c0];
        float aa[4] = {av.x, av.y, av.z, av.w};
        float ww[4] = {wv.x, wv.y, wv.z, wv.w};
#pragma unroll
        for (int i = 0; i < 4; i++)
#pragma unroll
            for (int j = 0; j < 4; j++)
                acc[i][j] = fmaf(aa[i], ww[j], acc[i][j]);
    }
#pragma unroll
    for (int i = 0; i < 4; i++) {
        int node = node0 + n0 + i;
        if (node >= NN) continue;
        float v[4];
#pragma unroll
        for (int j = 0; j < 4; j++) v[j] = tanhf(acc[i][j]);
        if (POOL) {
            int g = batch[node] * DD + c0;
#pragma unroll
            for (int j = 0; j < 4; j++) {
                float x = v[j];
                unsigned enc = (x >= 0.f) ? (__float_as_uint(x) | 0x80000000u)
                                          : ~__float_as_uint(x);
                atomicMax(&g_gmax[g + j], enc);
                atomicAdd(&g_gsum[g + j], x);
            }
        } else {
            float di = g_dinv[node];
            __half2* o = (__half2*)(g_feat + node * DD + c0);
            o[0] = __floats2half2_rn(di * v[0], di * v[1]);
            o[1] = __floats2half2_rn(di * v[2], di * v[3]);
        }
    }
}

// ---------------- readout ----------------------------------------------------
__global__ void k_out(const float* __restrict__ Wout, const float* __restrict__ bout,
                      float* __restrict__ out) {
    int g = blockIdx.x;
    int lane = threadIdx.x;
    float cnt = fmaxf((float)g_gcnt[g], 1.f);
    float s = 0.f;
    for (int f = lane; f < DD; f += 32) {
        unsigned e = g_gmax[g * DD + f];
        float mx = (e & 0x80000000u) ? __uint_as_float(e & 0x7FFFFFFFu)
                                     : __uint_as_float(~e);
        float mn = g_gsum[g * DD + f] / cnt;
        s += mx * Wout[f] + mn * Wout[DD + f];
    }
#pragma unroll
    for (int o = 16; o > 0; o >>= 1) s += __shfl_down_sync(0xFFFFFFFFu, s, o);
    if (lane == 0) out[g] = s + bout[0];
}

// ---------------- launch ----------------------------------------------------
extern "C" void kernel_launch(void* const* d_in, const int* in_sizes, int n_in,
                              void* d_out, int out_size) {
    const float* x     = (const float*)d_in[0];
    const int*   ei    = (const int*)d_in[1];
    const int*   batch = (const int*)d_in[2];
    const float* W0    = (const float*)d_in[3];
    const float* b0    = (const float*)d_in[4];
    const float* W1    = (const float*)d_in[5];
    const float* b1    = (const float*)d_in[6];
    const float* W2    = (const float*)d_in[7];
    const float* b2    = (const float*)d_in[8];
    const float* W3    = (const float*)d_in[9];
    const float* b3    = (const float*)d_in[10];
    const float* Wout  = (const float*)d_in[11];
    const float* bout  = (const float*)d_in[12];
    float* out = (float*)d_out;

    float* aggp;
    cudaGetSymbolAddress((void**)&aggp, g_agg);

    const int EB   = (EE + 255) / 256;        // 3125
    const int AGGB = (NN * 32 + 255) / 256;   // 6250 (warp per node)
    const int GB   = (NN + DD - 1) / DD;      // 782  (64-node GEMM tiles)

    k_init<<<256, 256>>>();
    k_count<<<EB, 256>>>(ei, batch);
    k_alloc<<<NBLK, 256>>>();
    k_fill<<<EB, 256>>>(ei);

    // layer 0: aggregate raw 9-dim features, GEMM K=9, store dinv-scaled fp16
    k_agg9<<<AGGB, 256>>>(x, aggp);
    k_gemm9<<<NBLK, 256>>>(aggp, W0, b0);
    // layers 1..2
    k_agg64h<<<AGGB, 256>>>(aggp);
    k_gemm64<0><<<GB, 256>>>(aggp, W1, b1, nullptr);
    k_agg64h<<<AGGB, 256>>>(aggp);
    k_gemm64<0><<<GB, 256>>>(aggp, W2, b2, nullptr);
    // layer 3 with fused pooling
    k_agg64h<<<AGGB, 256>>>(aggp);
    k_gemm64<1><<<GB, 256>>>(aggp, W3, b3, batch);

    k_out<<<GG, 32>>>(Wout, bout, out);
}